// round 7
// baseline (speedup 1.0000x reference)
#include <cuda_runtime.h>
#include <math.h>

// x: [2048, 512, 7, 7] fp32.
#define NCH      512
#define HW       49
#define SLAB     (NCH * HW)      // 25088 floats / sample
#define SLAB4    (SLAB / 4)      // 6272 float4 / sample
#define NTHREADS 512
#define NWARPS   (NTHREADS / 32) // 16
#define W_F4     (SLAB4 / NWARPS)// 392 float4 per warp region (= 32 channels exactly)
#define EPS      1e-5f

// SLAB4 = 512*12 + 128 (phase-4 tiling)
#define FULL_BATCHES 3
#define REM_THREADS  128

__global__ __launch_bounds__(NTHREADS, 4)
void ModelNew_25056839205377_kernel(const float* __restrict__ x,
                                    float* __restrict__ out)
{
    __shared__ float ch[NCH + 1];   // channel sums -> gates; +1 slack for c+1 read
    __shared__ float red[32];       // 16 sums, 16 sumsqs

    const int tid  = threadIdx.x;
    const int warp = tid >> 5;
    const int lane = tid & 31;
    const size_t base = (size_t)blockIdx.x * SLAB;
    const float* __restrict__ xp = x + base;
    const float4* __restrict__ x4 = (const float4*)xp;

    // ---- init: zero channel accumulators ----
    ch[tid] = 0.0f;
    if (tid == 0) ch[NCH] = 0.0f;
    __syncthreads();

    // ---- Phase 1: coalesced float4 loads, per-channel accumulation via SMEM atomics.
    // Warp w owns float4s [w*392, (w+1)*392) = channels [w*32, w*32+32) exactly
    // (1568 floats = 32*49, region ends on a channel boundary -> no cross-warp adds).
    {
        const int wbase = warp * W_F4;
        #pragma unroll
        for (int j = 0; j < 13; ++j) {                 // 392 = 12*32 + 8
            const int idx = lane + 32 * j;
            if (j < 12 || lane < 8) {
                const int i = wbase + idx;
                const float4 v = x4[i];                // default caching: keep in L2
                const int e = i * 4;
                const int c = e / HW;                  // mul+shift
                const int r = e - c * HW;              // 0..48
                float sA = v.x, sB = 0.0f;
                if (r < 48) sA += v.y; else sB += v.y;
                if (r < 47) sA += v.z; else sB += v.z;
                if (r < 46) sA += v.w; else sB += v.w;
                atomicAdd(&ch[c], sA);
                if (r >= 46) atomicAdd(&ch[c + 1], sB);
            }
        }
    }
    __syncthreads();

    // ---- Phase 2: per-thread y, block stats ----
    const float y = ch[tid] * (1.0f / HW);
    float ys = y, y2 = y * y;
    #pragma unroll
    for (int o = 16; o > 0; o >>= 1) {
        ys += __shfl_xor_sync(0xffffffffu, ys, o);
        y2 += __shfl_xor_sync(0xffffffffu, y2, o);
    }
    if (lane == 0) { red[warp] = ys; red[16 + warp] = y2; }
    __syncthreads();

    // ---- Phase 3: redundant final reduce in EVERY warp (drops one barrier),
    //      then gate[c] = exp(-z^2)  (C_PARAM=2 -> -0.5*2*z^2 = -z^2)
    {
        float s1 = (lane < 16) ? red[lane]      : 0.0f;
        float s2 = (lane < 16) ? red[16 + lane] : 0.0f;
        #pragma unroll
        for (int o = 8; o > 0; o >>= 1) {
            s1 += __shfl_xor_sync(0xffffffffu, s1, o);
            s2 += __shfl_xor_sync(0xffffffffu, s2, o);
        }
        s1 = __shfl_sync(0xffffffffu, s1, 0);
        s2 = __shfl_sync(0xffffffffu, s2, 0);
        const float m   = s1 * (1.0f / NCH);
        const float mx2 = s2 * (1.0f / NCH);
        const float var = fmaxf(mx2 - m * m, 0.0f);
        const float inv = rsqrtf(var + EPS);
        const float z   = (y - m) * inv;
        ch[tid] = __expf(-z * z);   // overwrite sum with gate (only owner writes)
    }
    __syncthreads();

    // ---- Phase 4: re-read x (L2-hit, evict-first), gate, stream store ----
    float4* __restrict__ o4 = (float4*)(out + base);

    #pragma unroll
    for (int b = 0; b < FULL_BATCHES; ++b) {
        const int i0 = tid + (4 * b) * NTHREADS;
        float4 v0 = __ldcs(x4 + i0 + 0 * NTHREADS);
        float4 v1 = __ldcs(x4 + i0 + 1 * NTHREADS);
        float4 v2 = __ldcs(x4 + i0 + 2 * NTHREADS);
        float4 v3 = __ldcs(x4 + i0 + 3 * NTHREADS);
        #pragma unroll
        for (int k = 0; k < 4; ++k) {
            float4& v = (k == 0) ? v0 : (k == 1) ? v1 : (k == 2) ? v2 : v3;
            const int e = (i0 + k * NTHREADS) * 4;
            const int c = e / HW;
            const int r = e - c * HW;
            const float g0 = ch[c];
            const float gn = ch[c + 1];
            v.x *= g0;
            v.y *= (r < 48) ? g0 : gn;
            v.z *= (r < 47) ? g0 : gn;
            v.w *= (r < 46) ? g0 : gn;
            __stcs(o4 + i0 + k * NTHREADS, v);
        }
    }
    if (tid < REM_THREADS) {
        const int i = tid + 12 * NTHREADS;
        float4 v = __ldcs(x4 + i);
        const int e = i * 4;
        const int c = e / HW;
        const int r = e - c * HW;
        const float g0 = ch[c];
        const float gn = ch[c + 1];
        v.x *= g0;
        v.y *= (r < 48) ? g0 : gn;
        v.z *= (r < 47) ? g0 : gn;
        v.w *= (r < 46) ? g0 : gn;
        __stcs(o4 + i, v);
    }
}

extern "C" void kernel_launch(void* const* d_in, const int* in_sizes, int n_in,
                              void* d_out, int out_size)
{
    const float* x = (const float*)d_in[0];
    float* out = (float*)d_out;
    const int nblocks = in_sizes[0] / SLAB;   // 2048 samples
    ModelNew_25056839205377_kernel<<<nblocks, NTHREADS>>>(x, out);
}

// round 8
// speedup vs baseline: 1.3263x; 1.3263x over previous
#include <cuda_runtime.h>
#include <math.h>

// x: [2048, 512, 7, 7] fp32.
#define NCH      512
#define HW       49
#define SLAB     (NCH * HW)      // 25088 floats / sample
#define SLAB4    (SLAB / 4)      // 6272 float4 / sample
#define NTHREADS 256
#define NWARPS   (NTHREADS / 32) // 8
#define CH_PER_W (NCH / NWARPS)  // 64 channels per warp
#define EPS      1e-5f

// SLAB4 = 6272 = 256*24 + 128 -> 6 batches of 4 strided iters + 128 remainder
#define FULL_BATCHES 6
#define REM_THREADS  128

__global__ __launch_bounds__(NTHREADS, 8)
void ModelNew_25056839205377_kernel(const float* __restrict__ x,
                                    float* __restrict__ out)
{
    __shared__ float ch[NCH + 1];   // y[c], later gate[c]; +1 slack for c+1 read
    __shared__ float red[18];       // 8 sums, 8 sumsqs, 2 bcast

    const int tid  = threadIdx.x;
    const int warp = tid >> 5;
    const int lane = tid & 31;
    const size_t base = (size_t)blockIdx.x * SLAB;
    const float* __restrict__ xp = x + base;

    // ---- Phase 1: y[c] = spatial mean. Each warp owns 64 channels. ----
    // 49 contiguous floats per channel: lanes 0..31 + predicated lanes 0..16.
    // unroll 8: independent shuffle chains hide SHFL latency.
    #pragma unroll 8
    for (int k = 0; k < CH_PER_W; ++k) {
        const int c = warp * CH_PER_W + k;
        const float* p = xp + c * HW;
        float s = p[lane] + ((lane < HW - 32) ? p[32 + lane] : 0.0f);
        #pragma unroll
        for (int o = 16; o > 0; o >>= 1)
            s += __shfl_xor_sync(0xffffffffu, s, o);
        if (lane == 0) ch[c] = s * (1.0f / HW);
    }
    __syncthreads();

    // ---- Phase 2: stats over 512 channels (thread t owns channels t, t+256) ----
    const float ya = ch[tid];
    const float yb = ch[tid + NTHREADS];
    float ys = ya + yb;
    float y2 = ya * ya + yb * yb;
    #pragma unroll
    for (int o = 16; o > 0; o >>= 1) {
        ys += __shfl_xor_sync(0xffffffffu, ys, o);
        y2 += __shfl_xor_sync(0xffffffffu, y2, o);
    }
    if (lane == 0) { red[warp] = ys; red[8 + warp] = y2; }
    __syncthreads();
    if (warp == 0) {
        float s1 = (lane < 8) ? red[lane]     : 0.0f;
        float s2 = (lane < 8) ? red[8 + lane] : 0.0f;
        #pragma unroll
        for (int o = 4; o > 0; o >>= 1) {
            s1 += __shfl_xor_sync(0xffffffffu, s1, o);
            s2 += __shfl_xor_sync(0xffffffffu, s2, o);
        }
        if (lane == 0) {
            const float m   = s1 * (1.0f / NCH);
            const float mx2 = s2 * (1.0f / NCH);
            const float var = fmaxf(mx2 - m * m, 0.0f);
            red[16] = m;
            red[17] = rsqrtf(var + EPS);
        }
    }
    __syncthreads();

    // ---- Phase 3: gate[c] = exp(-z^2)  (C_PARAM=2 -> -0.5*2*z^2 = -z^2) ----
    {
        const float m   = red[16];
        const float inv = red[17];
        const float za  = (ya - m) * inv;
        const float zb  = (yb - m) * inv;
        ch[tid]            = __expf(-za * za);
        ch[tid + NTHREADS] = __expf(-zb * zb);
    }
    if (tid == 0) ch[NCH] = 0.0f;   // slack slot for predicated c+1 reads
    __syncthreads();

    // ---- Phase 4: re-read x (L2-hit, evict-first), gate, stream store ----
    const float4* __restrict__ x4 = (const float4*)xp;
    float4* __restrict__ o4 = (float4*)(out + base);

    #pragma unroll
    for (int b = 0; b < FULL_BATCHES; ++b) {
        const int i0 = tid + (4 * b) * NTHREADS;
        // 4 independent 128b loads in flight before any store
        float4 v0 = __ldcs(x4 + i0 + 0 * NTHREADS);
        float4 v1 = __ldcs(x4 + i0 + 1 * NTHREADS);
        float4 v2 = __ldcs(x4 + i0 + 2 * NTHREADS);
        float4 v3 = __ldcs(x4 + i0 + 3 * NTHREADS);
        #pragma unroll
        for (int k = 0; k < 4; ++k) {
            float4& v = (k == 0) ? v0 : (k == 1) ? v1 : (k == 2) ? v2 : v3;
            const int e = (i0 + k * NTHREADS) * 4;
            const int c = e / HW;            // constant div -> mul+shift
            const int r = e - c * HW;        // 0..48
            const float g0 = ch[c];
            const float gn = ch[c + 1];
            v.x *= g0;
            v.y *= (r < 48) ? g0 : gn;
            v.z *= (r < 47) ? g0 : gn;
            v.w *= (r < 46) ? g0 : gn;
            __stcs(o4 + i0 + k * NTHREADS, v);
        }
    }
    // remainder: 6272 - 24*256 = 128 float4s
    if (tid < REM_THREADS) {
        const int i = tid + 24 * NTHREADS;
        float4 v = __ldcs(x4 + i);
        const int e = i * 4;
        const int c = e / HW;
        const int r = e - c * HW;
        const float g0 = ch[c];
        const float gn = ch[c + 1];
        v.x *= g0;
        v.y *= (r < 48) ? g0 : gn;
        v.z *= (r < 47) ? g0 : gn;
        v.w *= (r < 46) ? g0 : gn;
        __stcs(o4 + i, v);
    }
}

extern "C" void kernel_launch(void* const* d_in, const int* in_sizes, int n_in,
                              void* d_out, int out_size)
{
    const float* x = (const float*)d_in[0];
    float* out = (float*)d_out;
    const int nblocks = in_sizes[0] / SLAB;   // 2048 samples
    ModelNew_25056839205377_kernel<<<nblocks, NTHREADS>>>(x, out);
}